// round 1
// baseline (speedup 1.0000x reference)
#include <cuda_runtime.h>
#include <math.h>

#define B_DIM 8192
#define C_DIM 2048
#define F_DIM 2048

// Scratch (no allocations allowed) — row squared norms
__device__ float g_xx[B_DIM];   // sum_f x[b,f]^2   (unscaled)
__device__ float g_m2[C_DIM];   // sum_f means[c,f]^2

// ---------------------------------------------------------------------------
// Row sum-of-squares: one block per row, float4 loads.
// which==0 -> g_xx, which==1 -> g_m2
// ---------------------------------------------------------------------------
__global__ void __launch_bounds__(256)
rowsq_kernel(const float* __restrict__ mat, int which)
{
    __shared__ float sm[32];
    const int row = blockIdx.x;
    const float4* p = (const float4*)(mat + (size_t)row * F_DIM);
    float s = 0.f;
    for (int i = threadIdx.x; i < F_DIM / 4; i += blockDim.x) {
        float4 v = p[i];
        s += v.x * v.x + v.y * v.y + v.z * v.z + v.w * v.w;
    }
    // block reduce sum
    int lane = threadIdx.x & 31, wid = threadIdx.x >> 5;
    #pragma unroll
    for (int o = 16; o > 0; o >>= 1) s += __shfl_down_sync(0xffffffffu, s, o);
    if (lane == 0) sm[wid] = s;
    __syncthreads();
    if (threadIdx.x == 0) {
        float t = sm[0];
        #pragma unroll
        for (int w = 1; w < 8; w++) t += sm[w];
        if (which) g_m2[row] = t; else g_xx[row] = t;
    }
}

// ---------------------------------------------------------------------------
// Fused GEMM + distance epilogue.
// cross[b,c] = sum_f x[b,f]*means[c,f]   (NT GEMM, both K-contiguous)
// d2 = max(xx[b]/v^2 + m2[c] - 2*cross/v, 0);  dist = sqrt(d2)
// Writes exponent = -dist and cumulative_diff = dist.
// Tile 128x128x16, 256 threads, 8x8 micro-tile per thread.
// ---------------------------------------------------------------------------
__global__ void __launch_bounds__(256)
gemm_epi_kernel(const float* __restrict__ X, const float* __restrict__ Mn,
                const float* __restrict__ var,
                float* __restrict__ expo, float* __restrict__ dist)
{
    __shared__ float As[16][128];  // [k][m]
    __shared__ float Bs[16][128];  // [k][n]

    const int tid = threadIdx.x;
    const int tx = tid & 15;    // 0..15 -> n
    const int ty = tid >> 4;    // 0..15 -> m
    const int blockM = blockIdx.y * 128;
    const int blockN = blockIdx.x * 128;

    // loader mapping: 256 threads cover 128 rows x 16 cols (as float4) in 2 passes
    const int lrow = tid >> 2;          // 0..63
    const int lcol = (tid & 3) << 2;    // 0,4,8,12

    const float* Xp = X  + (size_t)blockM * F_DIM;
    const float* Mp = Mn + (size_t)blockN * F_DIM;

    float acc[8][8];
    #pragma unroll
    for (int i = 0; i < 8; i++)
        #pragma unroll
        for (int j = 0; j < 8; j++) acc[i][j] = 0.f;

    for (int k0 = 0; k0 < F_DIM; k0 += 16) {
        #pragma unroll
        for (int r = 0; r < 2; r++) {
            const int m = lrow + (r << 6);
            float4 va = *(const float4*)(Xp + (size_t)m * F_DIM + k0 + lcol);
            As[lcol + 0][m] = va.x;
            As[lcol + 1][m] = va.y;
            As[lcol + 2][m] = va.z;
            As[lcol + 3][m] = va.w;
            float4 vb = *(const float4*)(Mp + (size_t)m * F_DIM + k0 + lcol);
            Bs[lcol + 0][m] = vb.x;
            Bs[lcol + 1][m] = vb.y;
            Bs[lcol + 2][m] = vb.z;
            Bs[lcol + 3][m] = vb.w;
        }
        __syncthreads();

        #pragma unroll
        for (int k = 0; k < 16; k++) {
            float4 a0 = *(const float4*)&As[k][(ty << 2)];
            float4 a1 = *(const float4*)&As[k][64 + (ty << 2)];
            float4 b0 = *(const float4*)&Bs[k][(tx << 2)];
            float4 b1 = *(const float4*)&Bs[k][64 + (tx << 2)];
            float a[8] = {a0.x, a0.y, a0.z, a0.w, a1.x, a1.y, a1.z, a1.w};
            float b[8] = {b0.x, b0.y, b0.z, b0.w, b1.x, b1.y, b1.z, b1.w};
            #pragma unroll
            for (int i = 0; i < 8; i++)
                #pragma unroll
                for (int j = 0; j < 8; j++)
                    acc[i][j] = fmaf(a[i], b[j], acc[i][j]);
        }
        __syncthreads();
    }

    // -------- epilogue --------
    const float v    = *var;
    const float inv  = 1.0f / v;
    const float inv2 = inv * inv;
    const float n2i  = -2.0f * inv;

    int mi[8];
    float xxv[8];
    #pragma unroll
    for (int i = 0; i < 8; i++) {
        const int ml = (i < 4) ? ((ty << 2) + i) : (64 + (ty << 2) + i - 4);
        mi[i] = blockM + ml;
        xxv[i] = g_xx[mi[i]] * inv2;
    }
    const int nj0 = blockN + (tx << 2);
    const int nj1 = blockN + 64 + (tx << 2);
    float m2v[8];
    #pragma unroll
    for (int j = 0; j < 4; j++) {
        m2v[j]     = g_m2[nj0 + j];
        m2v[4 + j] = g_m2[nj1 + j];
    }

    #pragma unroll
    for (int i = 0; i < 8; i++) {
        const size_t base = (size_t)mi[i] * C_DIM;
        float d[8];
        #pragma unroll
        for (int j = 0; j < 8; j++) {
            float d2 = fmaf(n2i, acc[i][j], xxv[i] + m2v[j]);
            d2 = fmaxf(d2, 0.f);
            d[j] = sqrtf(d2);
        }
        float4 d0 = make_float4(d[0], d[1], d[2], d[3]);
        float4 d1 = make_float4(d[4], d[5], d[6], d[7]);
        float4 e0 = make_float4(-d[0], -d[1], -d[2], -d[3]);
        float4 e1 = make_float4(-d[4], -d[5], -d[6], -d[7]);
        *(float4*)(dist + base + nj0) = d0;
        *(float4*)(dist + base + nj1) = d1;
        *(float4*)(expo + base + nj0) = e0;
        *(float4*)(expo + base + nj1) = e1;
    }
}

// ---------------------------------------------------------------------------
// Row softmax over C=2048: one block (256 threads) per row, values held in
// registers (2x float4 per thread), two block reductions (max, sum).
// ---------------------------------------------------------------------------
__global__ void __launch_bounds__(256)
softmax_kernel(const float* __restrict__ expo, float* __restrict__ probs)
{
    __shared__ float sm[32];
    const int row = blockIdx.x;
    const int t = threadIdx.x;
    const float4* e = (const float4*)(expo + (size_t)row * C_DIM);
    float4* p = (float4*)(probs + (size_t)row * C_DIM);

    float4 v0 = e[t];
    float4 v1 = e[t + 256];

    // --- block max ---
    float mx = fmaxf(fmaxf(fmaxf(v0.x, v0.y), fmaxf(v0.z, v0.w)),
                     fmaxf(fmaxf(v1.x, v1.y), fmaxf(v1.z, v1.w)));
    int lane = t & 31, wid = t >> 5;
    #pragma unroll
    for (int o = 16; o > 0; o >>= 1) mx = fmaxf(mx, __shfl_down_sync(0xffffffffu, mx, o));
    if (lane == 0) sm[wid] = mx;
    __syncthreads();
    if (t == 0) {
        float m = sm[0];
        #pragma unroll
        for (int w = 1; w < 8; w++) m = fmaxf(m, sm[w]);
        sm[0] = m;
    }
    __syncthreads();
    mx = sm[0];
    __syncthreads();

    // --- exp + block sum ---
    float4 x0, x1;
    x0.x = expf(v0.x - mx); x0.y = expf(v0.y - mx);
    x0.z = expf(v0.z - mx); x0.w = expf(v0.w - mx);
    x1.x = expf(v1.x - mx); x1.y = expf(v1.y - mx);
    x1.z = expf(v1.z - mx); x1.w = expf(v1.w - mx);
    float s = x0.x + x0.y + x0.z + x0.w + x1.x + x1.y + x1.z + x1.w;
    #pragma unroll
    for (int o = 16; o > 0; o >>= 1) s += __shfl_down_sync(0xffffffffu, s, o);
    if (lane == 0) sm[wid] = s;
    __syncthreads();
    if (t == 0) {
        float acc = sm[0];
        #pragma unroll
        for (int w = 1; w < 8; w++) acc += sm[w];
        sm[0] = acc;
    }
    __syncthreads();
    const float rinv = 1.0f / sm[0];

    x0.x *= rinv; x0.y *= rinv; x0.z *= rinv; x0.w *= rinv;
    x1.x *= rinv; x1.y *= rinv; x1.z *= rinv; x1.w *= rinv;
    p[t] = x0;
    p[t + 256] = x1;
}

// ---------------------------------------------------------------------------
extern "C" void kernel_launch(void* const* d_in, const int* in_sizes, int n_in,
                              void* d_out, int out_size)
{
    const float* x     = (const float*)d_in[0];   // [B, F]
    const float* means = (const float*)d_in[1];   // [C, F]
    const float* var   = (const float*)d_in[2];   // [1]

    float* probs = (float*)d_out;                         // [B, C]
    float* expo  = probs + (size_t)B_DIM * C_DIM;         // [B, C]
    float* dist  = expo  + (size_t)B_DIM * C_DIM;         // [B, C]

    rowsq_kernel<<<B_DIM, 256>>>(x, 0);
    rowsq_kernel<<<C_DIM, 256>>>(means, 1);
    gemm_epi_kernel<<<dim3(C_DIM / 128, B_DIM / 128), 256>>>(x, means, var, expo, dist);
    softmax_kernel<<<B_DIM, 256>>>(expo, probs);
}

// round 3
// speedup vs baseline: 2.8472x; 2.8472x over previous
#include <cuda_runtime.h>
#include <stdint.h>
#include <math.h>

#define B_DIM 8192
#define C_DIM 2048
#define F_DIM 2048

#define BM 128
#define BN 128
#define BK 32
#define NKI (F_DIM / BK)     // 64 k-iterations
#define NSTG 4
#define ASTRIDE 36           // padded float stride (conflict-free: bank=4*lr+lq)
#define STAGE_FLOATS (2 * 128 * ASTRIDE)           // A tile + B tile per stage
#define SMEM_GEMM (NSTG * STAGE_FLOATS * 4)        // bytes

// ---------------- device scratch (no allocations allowed) -------------------
__device__ float g_A [(size_t)B_DIM * F_DIM];   // x/var, rounded to tf32
__device__ float g_Bm[(size_t)C_DIM * F_DIM];   // means, rounded to tf32
__device__ float g_xx[B_DIM];                   // ||x/var||^2 (exact fp32)
__device__ float g_m2[C_DIM];                   // ||means||^2

// ---------------- helpers ----------------------------------------------------
__device__ __forceinline__ uint32_t smem_u32(const void* p) {
    uint32_t a;
    asm("{ .reg .u64 t; cvta.to.shared.u64 t, %1; cvt.u32.u64 %0, t; }" : "=r"(a) : "l"(p));
    return a;
}
__device__ __forceinline__ float tf32_round(float v) {
    uint32_t u;
    asm("cvt.rna.tf32.f32 %0, %1;" : "=r"(u) : "f"(v));
    return __uint_as_float(u);
}
#define CP_ASYNC16(dst, src) \
    asm volatile("cp.async.cg.shared.global [%0], [%1], 16;" :: "r"(dst), "l"(src))
#define CP_COMMIT() asm volatile("cp.async.commit_group;" ::: "memory")
#define CP_WAIT(n)  asm volatile("cp.async.wait_group %0;" :: "n"(n) : "memory")

__device__ __forceinline__ void mma_tf32(float c[4], uint32_t a0, uint32_t a1,
                                         uint32_t a2, uint32_t a3,
                                         uint32_t b0, uint32_t b1) {
    asm volatile(
        "mma.sync.aligned.m16n8k8.row.col.f32.tf32.tf32.f32 "
        "{%0,%1,%2,%3}, {%4,%5,%6,%7}, {%8,%9}, {%0,%1,%2,%3};"
        : "+f"(c[0]), "+f"(c[1]), "+f"(c[2]), "+f"(c[3])
        : "r"(a0), "r"(a1), "r"(a2), "r"(a3), "r"(b0), "r"(b1));
}

// ---------------------------------------------------------------------------
// Convert: scale (x only) + round-to-tf32 + row squared norm.
// x_mode=1: g_A = tf32(x/var), g_xx = ||x/var||^2
// x_mode=0: g_Bm = tf32(means), g_m2 = ||means||^2
// ---------------------------------------------------------------------------
__global__ void __launch_bounds__(256)
convert_kernel(const float* __restrict__ src, const float* __restrict__ varp, int x_mode)
{
    __shared__ float sm[8];
    const int row = blockIdx.x;
    const float inv = x_mode ? (1.0f / varp[0]) : 1.0f;
    float* dst = (x_mode ? g_A : g_Bm) + (size_t)row * F_DIM;
    const float4* p = (const float4*)(src + (size_t)row * F_DIM);

    float s = 0.f;
    for (int j = threadIdx.x; j < F_DIM / 4; j += 256) {
        float4 v = p[j];
        float a0 = v.x * inv, a1 = v.y * inv, a2 = v.z * inv, a3 = v.w * inv;
        s += a0 * a0 + a1 * a1 + a2 * a2 + a3 * a3;
        float4 o = make_float4(tf32_round(a0), tf32_round(a1),
                               tf32_round(a2), tf32_round(a3));
        *(float4*)(dst + j * 4) = o;
    }
    int lane = threadIdx.x & 31, wid = threadIdx.x >> 5;
    #pragma unroll
    for (int o = 16; o > 0; o >>= 1) s += __shfl_down_sync(0xffffffffu, s, o);
    if (lane == 0) sm[wid] = s;
    __syncthreads();
    if (threadIdx.x == 0) {
        float t = sm[0];
        #pragma unroll
        for (int w = 1; w < 8; w++) t += sm[w];
        (x_mode ? g_xx : g_m2)[row] = t;
    }
}

// ---------------------------------------------------------------------------
// TF32 mma.sync GEMM (NT: both operands K-contiguous) + fused distance epilogue.
// 128x128x32 block tile, 8 warps 2x4, warp tile 64x32, 4-stage cp.async.
// ---------------------------------------------------------------------------
__global__ void __launch_bounds__(256, 1)
gemm_kernel(float* __restrict__ expo, float* __restrict__ dist)
{
    extern __shared__ float smem[];
    float* As0 = smem;                       // per stage: [128][ASTRIDE]
    float* Bs0 = smem + 128 * ASTRIDE;       // per stage: [128][ASTRIDE]

    const int tid  = threadIdx.x;
    const int wid  = tid >> 5;
    const int lane = tid & 31;
    const int lq   = lane & 3;      // k offset within fragment
    const int lr   = lane >> 2;     // row offset within fragment
    const int wm   = (wid >> 2) * 64;   // warp M offset (0,64)
    const int wn   = (wid & 3) * 32;    // warp N offset (0,32,64,96)
    const int blockM = blockIdx.y * BM;
    const int blockN = blockIdx.x * BN;

    // loader mapping: 1024 16B-chunks per operand; 256 threads x 4 chunks
    // chunk id -> row m = id>>3, k-quad kq = id&7
    const uint32_t sbase = smem_u32(smem);

    float acc[4][4][4];   // [mt][nt][reg]
    #pragma unroll
    for (int i = 0; i < 4; i++)
        #pragma unroll
        for (int j = 0; j < 4; j++)
            #pragma unroll
            for (int e = 0; e < 4; e++) acc[i][j][e] = 0.f;

    const float* gA = g_A  + (size_t)blockM * F_DIM;
    const float* gB = g_Bm + (size_t)blockN * F_DIM;

    // ---- load one stage ----
    auto load_stage = [&](int stage, int kiter) {
        const uint32_t abase = sbase + (uint32_t)(stage * STAGE_FLOATS) * 4u;
        const uint32_t bbase = abase + 128u * ASTRIDE * 4u;
        const int k0 = kiter * BK;
        #pragma unroll
        for (int t = 0; t < 4; t++) {
            int id = tid + (t << 8);
            int m = id >> 3, kq = id & 7;
            CP_ASYNC16(abase + (uint32_t)(m * ASTRIDE + kq * 4) * 4u,
                       gA + (size_t)m * F_DIM + k0 + kq * 4);
        }
        #pragma unroll
        for (int t = 0; t < 4; t++) {
            int id = tid + (t << 8);
            int m = id >> 3, kq = id & 7;
            CP_ASYNC16(bbase + (uint32_t)(m * ASTRIDE + kq * 4) * 4u,
                       gB + (size_t)m * F_DIM + k0 + kq * 4);
        }
    };

    // prologue: stages 0..2
    load_stage(0, 0); CP_COMMIT();
    load_stage(1, 1); CP_COMMIT();
    load_stage(2, 2); CP_COMMIT();

    for (int i = 0; i < NKI; i++) {
        const int nxt = i + NSTG - 1;
        if (nxt < NKI) load_stage(nxt & 3, nxt);
        CP_COMMIT();                 // always commit to keep group count fixed
        CP_WAIT(NSTG - 1);           // stage i's data resident
        __syncthreads();

        const float* A = As0 + (i & 3) * STAGE_FLOATS;
        const float* Bf = Bs0 + (i & 3) * STAGE_FLOATS;

        #pragma unroll
        for (int kk = 0; kk < BK; kk += 8) {
            uint32_t a[4][4], b[4][2];
            #pragma unroll
            for (int mt = 0; mt < 4; mt++) {
                const int r0 = wm + mt * 16 + lr;
                a[mt][0] = __float_as_uint(A[(r0)     * ASTRIDE + kk + lq]);
                a[mt][1] = __float_as_uint(A[(r0 + 8) * ASTRIDE + kk + lq]);
                a[mt][2] = __float_as_uint(A[(r0)     * ASTRIDE + kk + 4 + lq]);
                a[mt][3] = __float_as_uint(A[(r0 + 8) * ASTRIDE + kk + 4 + lq]);
            }
            #pragma unroll
            for (int nt = 0; nt < 4; nt++) {
                const int n0 = wn + nt * 8 + lr;
                b[nt][0] = __float_as_uint(Bf[n0 * ASTRIDE + kk + lq]);
                b[nt][1] = __float_as_uint(Bf[n0 * ASTRIDE + kk + 4 + lq]);
            }
            #pragma unroll
            for (int mt = 0; mt < 4; mt++)
                #pragma unroll
                for (int nt = 0; nt < 4; nt++)
                    mma_tf32(acc[mt][nt], a[mt][0], a[mt][1], a[mt][2], a[mt][3],
                             b[nt][0], b[nt][1]);
        }
        __syncthreads();   // compute done before this stage buffer is refilled
    }

    // -------- epilogue: d = sqrt(max(xx + m2 - 2*cross, 0)) --------
    #pragma unroll
    for (int mt = 0; mt < 4; mt++) {
        const int r0 = blockM + wm + mt * 16 + lr;
        const int r1 = r0 + 8;
        const float xx0 = g_xx[r0];
        const float xx1 = g_xx[r1];
        #pragma unroll
        for (int nt = 0; nt < 4; nt++) {
            const int c0 = blockN + wn + nt * 8 + 2 * lq;
            const float2 m2 = *(const float2*)(g_m2 + c0);
            float d00 = sqrtf(fmaxf(fmaf(-2.f, acc[mt][nt][0], xx0 + m2.x), 0.f));
            float d01 = sqrtf(fmaxf(fmaf(-2.f, acc[mt][nt][1], xx0 + m2.y), 0.f));
            float d10 = sqrtf(fmaxf(fmaf(-2.f, acc[mt][nt][2], xx1 + m2.x), 0.f));
            float d11 = sqrtf(fmaxf(fmaf(-2.f, acc[mt][nt][3], xx1 + m2.y), 0.f));
            *(float2*)(dist + (size_t)r0 * C_DIM + c0) = make_float2(d00, d01);
            *(float2*)(dist + (size_t)r1 * C_DIM + c0) = make_float2(d10, d11);
            *(float2*)(expo + (size_t)r0 * C_DIM + c0) = make_float2(-d00, -d01);
            *(float2*)(expo + (size_t)r1 * C_DIM + c0) = make_float2(-d10, -d11);
        }
    }
}

// ---------------------------------------------------------------------------
// Row softmax over C=2048: one block per row.
// ---------------------------------------------------------------------------
__global__ void __launch_bounds__(256)
softmax_kernel(const float* __restrict__ expo, float* __restrict__ probs)
{
    __shared__ float sm[32];
    const int row = blockIdx.x;
    const int t = threadIdx.x;
    const float4* e = (const float4*)(expo + (size_t)row * C_DIM);
    float4* p = (float4*)(probs + (size_t)row * C_DIM);

    float4 v0 = e[t];
    float4 v1 = e[t + 256];

    float mx = fmaxf(fmaxf(fmaxf(v0.x, v0.y), fmaxf(v0.z, v0.w)),
                     fmaxf(fmaxf(v1.x, v1.y), fmaxf(v1.z, v1.w)));
    int lane = t & 31, wid = t >> 5;
    #pragma unroll
    for (int o = 16; o > 0; o >>= 1) mx = fmaxf(mx, __shfl_down_sync(0xffffffffu, mx, o));
    if (lane == 0) sm[wid] = mx;
    __syncthreads();
    if (t == 0) {
        float m = sm[0];
        #pragma unroll
        for (int w = 1; w < 8; w++) m = fmaxf(m, sm[w]);
        sm[0] = m;
    }
    __syncthreads();
    mx = sm[0];
    __syncthreads();

    float4 x0, x1;
    x0.x = expf(v0.x - mx); x0.y = expf(v0.y - mx);
    x0.z = expf(v0.z - mx); x0.w = expf(v0.w - mx);
    x1.x = expf(v1.x - mx); x1.y = expf(v1.y - mx);
    x1.z = expf(v1.z - mx); x1.w = expf(v1.w - mx);
    float s = x0.x + x0.y + x0.z + x0.w + x1.x + x1.y + x1.z + x1.w;
    #pragma unroll
    for (int o = 16; o > 0; o >>= 1) s += __shfl_down_sync(0xffffffffu, s, o);
    if (lane == 0) sm[wid] = s;
    __syncthreads();
    if (t == 0) {
        float acc = sm[0];
        #pragma unroll
        for (int w = 1; w < 8; w++) acc += sm[w];
        sm[0] = acc;
    }
    __syncthreads();
    const float rinv = 1.0f / sm[0];

    x0.x *= rinv; x0.y *= rinv; x0.z *= rinv; x0.w *= rinv;
    x1.x *= rinv; x1.y *= rinv; x1.z *= rinv; x1.w *= rinv;
    p[t] = x0;
    p[t + 256] = x1;
}

// ---------------------------------------------------------------------------
extern "C" void kernel_launch(void* const* d_in, const int* in_sizes, int n_in,
                              void* d_out, int out_size)
{
    const float* x     = (const float*)d_in[0];
    const float* means = (const float*)d_in[1];
    const float* var   = (const float*)d_in[2];

    float* probs = (float*)d_out;
    float* expo  = probs + (size_t)B_DIM * C_DIM;
    float* dist  = expo  + (size_t)B_DIM * C_DIM;

    cudaFuncSetAttribute(gemm_kernel, cudaFuncAttributeMaxDynamicSharedMemorySize, SMEM_GEMM);

    convert_kernel<<<B_DIM, 256>>>(x, var, 1);
    convert_kernel<<<C_DIM, 256>>>(means, var, 0);
    gemm_kernel<<<dim3(C_DIM / BN, B_DIM / BM), 256, SMEM_GEMM>>>(expo, dist);
    softmax_kernel<<<B_DIM, 256>>>(expo, probs);
}

// round 4
// speedup vs baseline: 3.2061x; 1.1261x over previous
#include <cuda_runtime.h>
#include <stdint.h>
#include <math.h>

#define B_DIM 8192
#define C_DIM 2048
#define F_DIM 2048

#define BM 128
#define BN 128
#define BK 32
#define NKI (F_DIM / BK)     // 64 k-iterations
#define NSTG 4
#define ROWW 32                                   // words per row (no pad; XOR swizzle)
#define STAGE_FLOATS (2 * 128 * ROWW)             // A tile + B tile per stage
#define SMEM_GEMM (NSTG * STAGE_FLOATS * 4)       // 128 KB

// ---------------- device scratch (no allocations allowed) -------------------
// K-PERMUTED layout: within each 16-float k-group g, element k is stored at
// slot g*16 + (k%4)*4 + (k/4)%4.  => thread lq's fragment k-values
// {lq, lq+4, lq+8, lq+12} are CONTIGUOUS (one float4).
__device__ float g_A [(size_t)B_DIM * F_DIM];   // tf32(x/var), k-permuted
__device__ float g_Bm[(size_t)C_DIM * F_DIM];   // tf32(means), k-permuted
__device__ float g_xx[B_DIM];                   // ||x/var||^2 (exact fp32)
__device__ float g_m2[C_DIM];                   // ||means||^2

// ---------------- helpers ----------------------------------------------------
__device__ __forceinline__ uint32_t smem_u32(const void* p) {
    uint32_t a;
    asm("{ .reg .u64 t; cvta.to.shared.u64 t, %1; cvt.u32.u64 %0, t; }" : "=r"(a) : "l"(p));
    return a;
}
__device__ __forceinline__ float tf32_round(float v) {
    uint32_t u;
    asm("cvt.rna.tf32.f32 %0, %1;" : "=r"(u) : "f"(v));
    return __uint_as_float(u);
}
#define CP_ASYNC16(dst, src) \
    asm volatile("cp.async.cg.shared.global [%0], [%1], 16;" :: "r"(dst), "l"(src))
#define CP_COMMIT() asm volatile("cp.async.commit_group;" ::: "memory")
#define CP_WAIT(n)  asm volatile("cp.async.wait_group %0;" :: "n"(n) : "memory")

__device__ __forceinline__ void mma_tf32(float c[4], uint32_t a0, uint32_t a1,
                                         uint32_t a2, uint32_t a3,
                                         uint32_t b0, uint32_t b1) {
    asm volatile(
        "mma.sync.aligned.m16n8k8.row.col.f32.tf32.tf32.f32 "
        "{%0,%1,%2,%3}, {%4,%5,%6,%7}, {%8,%9}, {%0,%1,%2,%3};"
        : "+f"(c[0]), "+f"(c[1]), "+f"(c[2]), "+f"(c[3])
        : "r"(a0), "r"(a1), "r"(a2), "r"(a3), "r"(b0), "r"(b1));
}

// ---------------------------------------------------------------------------
// Convert: scale (x only) + tf32 round + row ||.||^2 + K-PERMUTED store.
// ---------------------------------------------------------------------------
__global__ void __launch_bounds__(256)
convert_kernel(const float* __restrict__ src, const float* __restrict__ varp, int x_mode)
{
    __shared__ float sm[8];
    const int row = blockIdx.x;
    const float inv = x_mode ? (1.0f / varp[0]) : 1.0f;
    float* dst = (x_mode ? g_A : g_Bm) + (size_t)row * F_DIM;
    const float4* p = (const float4*)(src + (size_t)row * F_DIM);

    float s = 0.f;
    for (int j = threadIdx.x; j < F_DIM / 4; j += 256) {
        float4 v = p[j];
        float a0 = v.x * inv, a1 = v.y * inv, a2 = v.z * inv, a3 = v.w * inv;
        s += a0 * a0 + a1 * a1 + a2 * a2 + a3 * a3;
        // k = 4j+e ; group g = j>>2 ; slot = g*16 + e*4 + (j&3)
        const int base = (j >> 2) * 16 + (j & 3);
        dst[base +  0] = tf32_round(a0);
        dst[base +  4] = tf32_round(a1);
        dst[base +  8] = tf32_round(a2);
        dst[base + 12] = tf32_round(a3);
    }
    int lane = threadIdx.x & 31, wid = threadIdx.x >> 5;
    #pragma unroll
    for (int o = 16; o > 0; o >>= 1) s += __shfl_down_sync(0xffffffffu, s, o);
    if (lane == 0) sm[wid] = s;
    __syncthreads();
    if (threadIdx.x == 0) {
        float t = sm[0];
        #pragma unroll
        for (int w = 1; w < 8; w++) t += sm[w];
        (x_mode ? g_xx : g_m2)[row] = t;
    }
}

// ---------------------------------------------------------------------------
// TF32 mma.sync GEMM + fused distance epilogue.
// 128x128x32 tile, 8 warps 2x4 (warp tile 64x32), 4-stage cp.async,
// ONE __syncthreads per k-iter, LDS.128 fragment loads, XOR-16 row swizzle.
// ---------------------------------------------------------------------------
__global__ void __launch_bounds__(256, 1)
gemm_kernel(float* __restrict__ expo, float* __restrict__ dist)
{
    extern __shared__ float smem[];

    const int tid  = threadIdx.x;
    const int wid  = tid >> 5;
    const int lane = tid & 31;
    const int lq   = lane & 3;
    const int lr   = lane >> 2;
    const int wm   = (wid >> 2) * 64;   // warp M offset (0,64)
    const int wn   = (wid & 3) * 32;    // warp N offset (0,32,64,96)
    const int blockM = blockIdx.y * BM;
    const int blockN = blockIdx.x * BN;

    const uint32_t sbase = smem_u32(smem);

    float acc[4][4][4];
    #pragma unroll
    for (int i = 0; i < 4; i++)
        #pragma unroll
        for (int j = 0; j < 4; j++)
            #pragma unroll
            for (int e = 0; e < 4; e++) acc[i][j][e] = 0.f;

    const float* gA = g_A  + (size_t)blockM * F_DIM;
    const float* gB = g_Bm + (size_t)blockN * F_DIM;

    // smem word offset for (row m, word w): m*32 + (w ^ ((m&1)<<4))
    auto load_stage = [&](int stage, int kiter) {
        const uint32_t abase = sbase + (uint32_t)(stage * STAGE_FLOATS) * 4u;
        const uint32_t bbase = abase + 128u * ROWW * 4u;
        const int k0 = kiter * BK;
        #pragma unroll
        for (int t = 0; t < 4; t++) {
            int id = tid + (t << 8);
            int m = id >> 3, c = id & 7;                 // c: 16B chunk (4 words)
            uint32_t w = (uint32_t)((c * 4) ^ ((m & 1) << 4));
            CP_ASYNC16(abase + (uint32_t)(m * ROWW + w) * 4u,
                       gA + (size_t)m * F_DIM + k0 + c * 4);
        }
        #pragma unroll
        for (int t = 0; t < 4; t++) {
            int id = tid + (t << 8);
            int m = id >> 3, c = id & 7;
            uint32_t w = (uint32_t)((c * 4) ^ ((m & 1) << 4));
            CP_ASYNC16(bbase + (uint32_t)(m * ROWW + w) * 4u,
                       gB + (size_t)m * F_DIM + k0 + c * 4);
        }
    };

    load_stage(0, 0); CP_COMMIT();
    load_stage(1, 1); CP_COMMIT();
    load_stage(2, 2); CP_COMMIT();

    for (int i = 0; i < NKI; i++) {
        CP_WAIT(NSTG - 2);
        __syncthreads();

        const float* A  = smem + (i & 3) * STAGE_FLOATS;
        const float* Bf = A + 128 * ROWW;

        #pragma unroll
        for (int g = 0; g < 2; g++) {               // 16-float k-group
            const int wbase = g * 16 + lq * 4;      // word within row (pre-swizzle)
            float4 a4l[4], a4h[4], b4[4];
            #pragma unroll
            for (int mt = 0; mt < 4; mt++) {
                const int r0 = wm + mt * 16 + lr;
                const int r1 = r0 + 8;
                a4l[mt] = *(const float4*)(A + r0 * ROWW + (wbase ^ ((r0 & 1) << 4)));
                a4h[mt] = *(const float4*)(A + r1 * ROWW + (wbase ^ ((r1 & 1) << 4)));
            }
            #pragma unroll
            for (int nt = 0; nt < 4; nt++) {
                const int n0 = wn + nt * 8 + lr;
                b4[nt] = *(const float4*)(Bf + n0 * ROWW + (wbase ^ ((n0 & 1) << 4)));
            }
            // sub-chunk 0: k = 16g + {lq, lq+4}  -> .x/.y
            #pragma unroll
            for (int mt = 0; mt < 4; mt++)
                #pragma unroll
                for (int nt = 0; nt < 4; nt++)
                    mma_tf32(acc[mt][nt],
                             __float_as_uint(a4l[mt].x), __float_as_uint(a4h[mt].x),
                             __float_as_uint(a4l[mt].y), __float_as_uint(a4h[mt].y),
                             __float_as_uint(b4[nt].x),  __float_as_uint(b4[nt].y));
            // sub-chunk 1: k = 16g+8 + {lq, lq+4} -> .z/.w
            #pragma unroll
            for (int mt = 0; mt < 4; mt++)
                #pragma unroll
                for (int nt = 0; nt < 4; nt++)
                    mma_tf32(acc[mt][nt],
                             __float_as_uint(a4l[mt].z), __float_as_uint(a4h[mt].z),
                             __float_as_uint(a4l[mt].w), __float_as_uint(a4h[mt].w),
                             __float_as_uint(b4[nt].z),  __float_as_uint(b4[nt].w));
        }

        const int nxt = i + NSTG - 1;
        if (nxt < NKI) load_stage(nxt & 3, nxt);
        CP_COMMIT();
    }

    // -------- epilogue: d = sqrt(max(xx + m2 - 2*cross, 0)) --------
    #pragma unroll
    for (int mt = 0; mt < 4; mt++) {
        const int r0 = blockM + wm + mt * 16 + lr;
        const int r1 = r0 + 8;
        const float xx0 = g_xx[r0];
        const float xx1 = g_xx[r1];
        #pragma unroll
        for (int nt = 0; nt < 4; nt++) {
            const int c0 = blockN + wn + nt * 8 + 2 * lq;
            const float2 m2 = *(const float2*)(g_m2 + c0);
            float d00 = sqrtf(fmaxf(fmaf(-2.f, acc[mt][nt][0], xx0 + m2.x), 0.f));
            float d01 = sqrtf(fmaxf(fmaf(-2.f, acc[mt][nt][1], xx0 + m2.y), 0.f));
            float d10 = sqrtf(fmaxf(fmaf(-2.f, acc[mt][nt][2], xx1 + m2.x), 0.f));
            float d11 = sqrtf(fmaxf(fmaf(-2.f, acc[mt][nt][3], xx1 + m2.y), 0.f));
            *(float2*)(dist + (size_t)r0 * C_DIM + c0) = make_float2(d00, d01);
            *(float2*)(dist + (size_t)r1 * C_DIM + c0) = make_float2(d10, d11);
            *(float2*)(expo + (size_t)r0 * C_DIM + c0) = make_float2(-d00, -d01);
            *(float2*)(expo + (size_t)r1 * C_DIM + c0) = make_float2(-d10, -d11);
        }
    }
}

// ---------------------------------------------------------------------------
// Row softmax over C=2048: one block per row.
// ---------------------------------------------------------------------------
__global__ void __launch_bounds__(256)
softmax_kernel(const float* __restrict__ expo, float* __restrict__ probs)
{
    __shared__ float sm[32];
    const int row = blockIdx.x;
    const int t = threadIdx.x;
    const float4* e = (const float4*)(expo + (size_t)row * C_DIM);
    float4* p = (float4*)(probs + (size_t)row * C_DIM);

    float4 v0 = e[t];
    float4 v1 = e[t + 256];

    float mx = fmaxf(fmaxf(fmaxf(v0.x, v0.y), fmaxf(v0.z, v0.w)),
                     fmaxf(fmaxf(v1.x, v1.y), fmaxf(v1.z, v1.w)));
    int lane = t & 31, wid = t >> 5;
    #pragma unroll
    for (int o = 16; o > 0; o >>= 1) mx = fmaxf(mx, __shfl_down_sync(0xffffffffu, mx, o));
    if (lane == 0) sm[wid] = mx;
    __syncthreads();
    if (t == 0) {
        float m = sm[0];
        #pragma unroll
        for (int w = 1; w < 8; w++) m = fmaxf(m, sm[w]);
        sm[0] = m;
    }
    __syncthreads();
    mx = sm[0];
    __syncthreads();

    float4 x0, x1;
    x0.x = expf(v0.x - mx); x0.y = expf(v0.y - mx);
    x0.z = expf(v0.z - mx); x0.w = expf(v0.w - mx);
    x1.x = expf(v1.x - mx); x1.y = expf(v1.y - mx);
    x1.z = expf(v1.z - mx); x1.w = expf(v1.w - mx);
    float s = x0.x + x0.y + x0.z + x0.w + x1.x + x1.y + x1.z + x1.w;
    #pragma unroll
    for (int o = 16; o > 0; o >>= 1) s += __shfl_down_sync(0xffffffffu, s, o);
    if (lane == 0) sm[wid] = s;
    __syncthreads();
    if (t == 0) {
        float acc = sm[0];
        #pragma unroll
        for (int w = 1; w < 8; w++) acc += sm[w];
        sm[0] = acc;
    }
    __syncthreads();
    const float rinv = 1.0f / sm[0];

    x0.x *= rinv; x0.y *= rinv; x0.z *= rinv; x0.w *= rinv;
    x1.x *= rinv; x1.y *= rinv; x1.z *= rinv; x1.w *= rinv;
    p[t] = x0;
    p[t + 256] = x1;
}

// ---------------------------------------------------------------------------
extern "C" void kernel_launch(void* const* d_in, const int* in_sizes, int n_in,
                              void* d_out, int out_size)
{
    const float* x     = (const float*)d_in[0];
    const float* means = (const float*)d_in[1];
    const float* var   = (const float*)d_in[2];

    float* probs = (float*)d_out;
    float* expo  = probs + (size_t)B_DIM * C_DIM;
    float* dist  = expo  + (size_t)B_DIM * C_DIM;

    cudaFuncSetAttribute(gemm_kernel, cudaFuncAttributeMaxDynamicSharedMemorySize, SMEM_GEMM);

    convert_kernel<<<B_DIM, 256>>>(x, var, 1);
    convert_kernel<<<C_DIM, 256>>>(means, var, 0);
    gemm_kernel<<<dim3(C_DIM / BN, B_DIM / BM), 256, SMEM_GEMM>>>(expo, dist);
    softmax_kernel<<<B_DIM, 256>>>(expo, probs);
}